// round 1
// baseline (speedup 1.0000x reference)
#include <cuda_runtime.h>
#include <cuda_bf16.h>
#include <cstdint>

#define B_ 1024
#define N_ 8192
#define K_ 4096
#define LOGN_ 13

// Map: position j -> index into info_bits row, or -1 if not an info position.
__device__ int g_is_info[N_];

__global__ void init_map_kernel() {
    int j = blockIdx.x * blockDim.x + threadIdx.x;
    if (j < N_) g_is_info[j] = -1;
}

__global__ void scatter_map_kernel(const int* __restrict__ info_set) {
    int k = blockIdx.x * blockDim.x + threadIdx.x;
    if (k < K_) g_is_info[info_set[k]] = k;
}

__global__ __launch_bounds__(256)
void polar_encoder_kernel(const float* __restrict__ info_bits,
                          const int*   __restrict__ u_random,
                          float*       __restrict__ out)
{
    __shared__ int su[N_];

    const int b = blockIdx.x;
    const int t = threadIdx.x;
    const int T = blockDim.x;

    const int*   ur_row = u_random  + (size_t)b * N_;
    const float* ib_row = info_bits + (size_t)b * K_;

    // Output layout (float32, concatenated flat):
    //   x : [0,            B*N)
    //   f : [B*N,        2*B*N)
    //   u : [2*B*N,      3*B*N)
    //   p : [3*B*N,      5*B*N)   (B,N,2)
    //   r : [5*B*N,      7*B*N)   (B,N,2)
    float* out_x = out;
    float* out_f = out + (size_t)1 * B_ * N_;
    float* out_u = out + (size_t)2 * B_ * N_;
    float* out_p = out + (size_t)3 * B_ * N_;
    float* out_r = out + (size_t)5 * B_ * N_;

    const size_t row_base = (size_t)b * N_;

    // Pass 1: build u row in smem, emit f/u/p/r in the same sweep (coalesced).
    #pragma unroll 4
    for (int j = t; j < N_; j += T) {
        int ur = ur_row[j];
        int ii = g_is_info[j];
        int uv, fv;
        if (ii >= 0) {
            uv = (int)ib_row[ii];   // info_bits in {0.0, 1.0}
            fv = 2;
        } else {
            uv = ur;
            fv = ur;
        }
        su[j] = uv;

        size_t idx = row_base + j;
        out_f[idx] = (float)fv;
        out_u[idx] = (float)uv;
        reinterpret_cast<float2*>(out_p)[idx] = make_float2(0.5f, 0.5f);
        reinterpret_cast<float2*>(out_r)[idx] = make_float2(1.0f - (float)ur, (float)ur);
    }
    __syncthreads();

    // In-place polar encode: for each stage d, su[i] ^= su[i|d] for (i&d)==0.
    // Stages commute; result is u * F^{tensor 13}.
    #pragma unroll
    for (int s = 0; s < LOGN_; s++) {
        const int d = 1 << s;
        for (int k = t; k < N_ / 2; k += T) {
            int i = ((k >> s) << (s + 1)) | (k & (d - 1));
            su[i] ^= su[i + d];
        }
        __syncthreads();
    }

    // Reference layout = bit-reversed permutation of the in-place result.
    #pragma unroll 4
    for (int j = t; j < N_; j += T) {
        int rj = (int)(__brev((unsigned)j) >> (32 - LOGN_));
        out_x[row_base + j] = (float)su[rj];
    }
}

extern "C" void kernel_launch(void* const* d_in, const int* in_sizes, int n_in,
                              void* d_out, int out_size) {
    const float* info_bits = (const float*)d_in[0];
    const int*   u_random  = (const int*)d_in[1];
    const int*   info_set  = (const int*)d_in[2];
    float* out = (float*)d_out;

    init_map_kernel<<<(N_ + 255) / 256, 256>>>();
    scatter_map_kernel<<<(K_ + 255) / 256, 256>>>(info_set);
    polar_encoder_kernel<<<B_, 256>>>(info_bits, u_random, out);
}

// round 2
// speedup vs baseline: 2.0411x; 2.0411x over previous
#include <cuda_runtime.h>
#include <cuda_bf16.h>
#include <cstdint>

#define B_ 1024
#define N_ 8192
#define K_ 4096

// Map: position j -> index into info_bits row, or -1 if frozen.
__device__ int g_map[N_];

// Single-block prologue: init + scatter with an in-block barrier.
__global__ __launch_bounds__(1024)
void build_map_kernel(const int* __restrict__ info_set) {
    int t = threadIdx.x;
    #pragma unroll
    for (int j = t; j < N_; j += 1024) g_map[j] = -1;
    __syncthreads();
    #pragma unroll
    for (int k = t; k < K_; k += 1024) g_map[info_set[k]] = k;
}

__global__ __launch_bounds__(256)
void polar_kernel(const float* __restrict__ info_bits,
                  const int*   __restrict__ u_random,
                  float*       __restrict__ out)
{
    // Packed final codeword: word (w*32 + L) holds elements
    // i = w*1024 + (L>>2)*128 + bit*4 + (L&3), bit = 0..31.
    __shared__ unsigned SW[256];

    const int b = blockIdx.x;
    const int t = threadIdx.x;
    const int w = t >> 5;       // warp id (0..7)
    const int l = t & 31;       // lane

    const int4*  ur4  = (const int4*)(u_random + (size_t)b * N_);
    const float* ib   = info_bits + (size_t)b * K_;
    const int4*  map4 = (const int4*)g_map;

    float* out_x = out;
    float* out_f = out + (size_t)1 * B_ * N_;
    float* out_u = out + (size_t)2 * B_ * N_;
    float* out_p = out + (size_t)3 * B_ * N_;   // (B,N,2)
    float* out_r = out + (size_t)5 * B_ * N_;   // (B,N,2)
    const size_t rb = (size_t)b * N_;

    unsigned myword = 0;

    // ---- Pass 1: coalesced load, emit f/u/p/r, ballot-pack u bits ----
    #pragma unroll
    for (int m = 0; m < 8; m++) {
        const int j0 = w * 1024 + m * 128 + l * 4;
        const int4 ur = ur4[j0 >> 2];
        const int4 mp = map4[j0 >> 2];

        int u0 = (mp.x >= 0) ? (int)ib[mp.x] : ur.x;
        int u1 = (mp.y >= 0) ? (int)ib[mp.y] : ur.y;
        int u2 = (mp.z >= 0) ? (int)ib[mp.z] : ur.z;
        int u3 = (mp.w >= 0) ? (int)ib[mp.w] : ur.w;
        int f0 = (mp.x >= 0) ? 2 : ur.x;
        int f1 = (mp.y >= 0) ? 2 : ur.y;
        int f2 = (mp.z >= 0) ? 2 : ur.z;
        int f3 = (mp.w >= 0) ? 2 : ur.w;

        const size_t o = rb + (size_t)j0;
        *(float4*)(out_f + o) = make_float4((float)f0, (float)f1, (float)f2, (float)f3);
        *(float4*)(out_u + o) = make_float4((float)u0, (float)u1, (float)u2, (float)u3);

        float4* pp = (float4*)(out_p + 2 * o);
        pp[0] = make_float4(0.5f, 0.5f, 0.5f, 0.5f);
        pp[1] = make_float4(0.5f, 0.5f, 0.5f, 0.5f);

        float4* rr = (float4*)(out_r + 2 * o);
        rr[0] = make_float4(1.0f - (float)ur.x, (float)ur.x,
                            1.0f - (float)ur.y, (float)ur.y);
        rr[1] = make_float4(1.0f - (float)ur.z, (float)ur.z,
                            1.0f - (float)ur.w, (float)ur.w);

        // Pack: ballot bit 'lane' of ballot_e = u bit of element (m*128 + lane*4 + e)
        unsigned b0 = __ballot_sync(0xFFFFFFFFu, u0);
        unsigned b1 = __ballot_sync(0xFFFFFFFFu, u1);
        unsigned b2 = __ballot_sync(0xFFFFFFFFu, u2);
        unsigned b3 = __ballot_sync(0xFFFFFFFFu, u3);
        if ((l >> 2) == m) {
            const int e = l & 3;
            myword = (e == 0) ? b0 : (e == 1) ? b1 : (e == 2) ? b2 : b3;
        }
    }

    // ---- Butterfly (stages commute). Element index bits in this packing:
    //   bits 0..1  -> L&3 (lane bits 0,1)
    //   bits 2..6  -> bit position in word
    //   bits 7..9  -> L>>2 (lane bits 2,3,4)
    //   bits 10..12-> warp id
    unsigned o1;
    o1 = __shfl_xor_sync(0xFFFFFFFFu, myword, 1);  if (!(l & 1))  myword ^= o1;  // d=1
    o1 = __shfl_xor_sync(0xFFFFFFFFu, myword, 2);  if (!(l & 2))  myword ^= o1;  // d=2
    myword ^= (myword >> 1)  & 0x55555555u;                                      // d=4
    myword ^= (myword >> 2)  & 0x33333333u;                                      // d=8
    myword ^= (myword >> 4)  & 0x0F0F0F0Fu;                                      // d=16
    myword ^= (myword >> 8)  & 0x00FF00FFu;                                      // d=32
    myword ^= (myword >> 16) & 0x0000FFFFu;                                      // d=64
    o1 = __shfl_xor_sync(0xFFFFFFFFu, myword, 4);  if (!(l & 4))  myword ^= o1;  // d=128
    o1 = __shfl_xor_sync(0xFFFFFFFFu, myword, 8);  if (!(l & 8))  myword ^= o1;  // d=256
    o1 = __shfl_xor_sync(0xFFFFFFFFu, myword, 16); if (!(l & 16)) myword ^= o1;  // d=512

    SW[t] = myword;
    __syncthreads();
    // d=1024, 2048, 4096: word-level XOR across warps (low-w threads write,
    // partners are read-only at each stage).
    if (!(w & 1)) SW[t] ^= SW[t + 32];
    __syncthreads();
    if (!(w & 2)) SW[t] ^= SW[t + 64];
    __syncthreads();
    if (!(w & 4)) SW[t] ^= SW[t + 128];
    __syncthreads();

    // ---- Pass 3: x[j] = packed_bit[brev13(j)], coalesced float4 stores ----
    #pragma unroll
    for (int m = 0; m < 8; m++) {
        const int j0 = m * 1024 + t * 4;                 // j0 multiple of 4
        const unsigned i0 = __brev((unsigned)j0) >> 19;  // bits 11,12 are 0
        const unsigned idx0 = ((i0 >> 10) << 5) | (((i0 >> 7) & 7) << 2) | (i0 & 3);
        const unsigned bit  = (i0 >> 2) & 31;
        // j bit0 -> i bit12 -> +128 words; j bit1 -> i bit11 -> +64 words
        const float x0 = (float)((SW[idx0]       >> bit) & 1u);
        const float x1 = (float)((SW[idx0 + 128] >> bit) & 1u);
        const float x2 = (float)((SW[idx0 + 64]  >> bit) & 1u);
        const float x3 = (float)((SW[idx0 + 192] >> bit) & 1u);
        *(float4*)(out_x + rb + (size_t)j0) = make_float4(x0, x1, x2, x3);
    }
}

extern "C" void kernel_launch(void* const* d_in, const int* in_sizes, int n_in,
                              void* d_out, int out_size) {
    const float* info_bits = (const float*)d_in[0];
    const int*   u_random  = (const int*)d_in[1];
    const int*   info_set  = (const int*)d_in[2];
    float* out = (float*)d_out;

    build_map_kernel<<<1, 1024>>>(info_set);
    polar_kernel<<<B_, 256>>>(info_bits, u_random, out);
}